// round 2
// baseline (speedup 1.0000x reference)
#include <cuda_runtime.h>
#include <cuda_bf16.h>
#include <stdint.h>

// Problem constants (fixed by the dataset)
#define MAXN 100000
#define MAXE 1600000
#define MAXEL 200000

// ---------------- static scratch (no allocations allowed) ----------------
__device__ float g_bufA[(size_t)MAXN * 128];   // GEMM output (dinv-scaled)
__device__ float g_bufB[(size_t)MAXN * 128];   // aggregated layer output
__device__ float g_dinv[MAXN];
__device__ int   g_cnt[MAXN];
__device__ int   g_cur[MAXN];
__device__ int   g_rowptr[MAXN + 1];
__device__ int   g_bsum[512];
__device__ int   g_boff[512];
__device__ int   g_esrc[MAXE];
__device__ int   g_is64;

// ---------------- index dtype detection ----------------
// JAX may deliver edge_index as int32 (x64 disabled) or int64. Random int32
// node ids misread as int64 are astronomically unlikely to all land in [0,N).
__global__ void detect_dtype_k(const void* ei, int n) {
    __shared__ int ok;
    if (threadIdx.x == 0) ok = 1;
    __syncthreads();
    const long long* p = (const long long*)ei;
    for (int i = threadIdx.x; i < 1024; i += blockDim.x) {
        long long v = p[i];
        if (v < 0 || v >= (long long)n) ok = 0;
    }
    __syncthreads();
    if (threadIdx.x == 0) g_is64 = ok;
}

__device__ __forceinline__ int eidx(const void* p, size_t i, int is64) {
    return is64 ? (int)((const long long*)p)[i] : ((const int*)p)[i];
}

// ---------------- degree / CSR build ----------------
__global__ void zero_k(int n) {
    int i = blockIdx.x * blockDim.x + threadIdx.x;
    if (i < n) { g_cnt[i] = 0; g_cur[i] = 0; }
}

__global__ void count_k(const void* ei, int E) {
    int e = blockIdx.x * blockDim.x + threadIdx.x;
    if (e >= E) return;
    int is64 = g_is64;
    int dst = eidx(ei, (size_t)E + e, is64);
    atomicAdd(&g_cnt[dst], 1);
}

__global__ void scan1_k(int n) {
    __shared__ int s[512];
    int t = threadIdx.x;
    int idx = blockIdx.x * 512 + t;
    int v = (idx < n) ? g_cnt[idx] : 0;
    s[t] = v;
    __syncthreads();
    #pragma unroll
    for (int off = 1; off < 512; off <<= 1) {
        int add = (t >= off) ? s[t - off] : 0;
        __syncthreads();
        s[t] += add;
        __syncthreads();
    }
    if (idx < n) g_rowptr[idx] = s[t] - v;       // exclusive (partial)
    if (t == 511) g_bsum[blockIdx.x] = s[511];   // block total
}

__global__ void scan2_k(int nb) {
    __shared__ int s[512];
    int t = threadIdx.x;
    int v = (t < nb) ? g_bsum[t] : 0;
    s[t] = v;
    __syncthreads();
    #pragma unroll
    for (int off = 1; off < 512; off <<= 1) {
        int add = (t >= off) ? s[t - off] : 0;
        __syncthreads();
        s[t] += add;
        __syncthreads();
    }
    g_boff[t] = s[t] - v;                         // exclusive block offsets
}

__global__ void scan3_k(int n, int E) {
    int idx = blockIdx.x * 512 + threadIdx.x;
    if (idx < n) g_rowptr[idx] += g_boff[blockIdx.x];
    if (idx == 0) g_rowptr[n] = E;
}

__global__ void dinv_k(int n) {
    int i = blockIdx.x * blockDim.x + threadIdx.x;
    if (i < n) g_dinv[i] = rsqrtf((float)g_cnt[i] + 1.0f);
}

__global__ void fill_k(const void* ei, int E) {
    int e = blockIdx.x * blockDim.x + threadIdx.x;
    if (e >= E) return;
    int is64 = g_is64;
    int src = eidx(ei, (size_t)e, is64);
    int dst = eidx(ei, (size_t)E + e, is64);
    int pos = g_rowptr[dst] + atomicAdd(&g_cur[dst], 1);
    g_esrc[pos] = src;
}

// ---------------- GEMM: out[row] = relu?(X[row]) @ W  * dinv[row] ----------------
// K = 128 fixed. TILE_M = 64, 256 threads, thread = 4 rows x (TN/16) cols.
template<int TN, bool RELU>
__global__ void gemm_k(const float* __restrict__ X, const float* __restrict__ W,
                       float* __restrict__ out, int n) {
    constexpr int CPT = TN / 16;
    __shared__ float XsT[16][65];
    __shared__ float Ws[16][TN];
    int tid = threadIdx.x;
    int tx = tid & 15, ty = tid >> 4;
    int m0 = blockIdx.x * 64;

    float acc[4][CPT];
    #pragma unroll
    for (int i = 0; i < 4; i++)
        #pragma unroll
        for (int j = 0; j < CPT; j++) acc[i][j] = 0.0f;

    int r = tid >> 2, q = tid & 3;   // X-tile loader mapping: 64 rows x 4 float4
    for (int k0 = 0; k0 < 128; k0 += 16) {
        float4 xv = make_float4(0.f, 0.f, 0.f, 0.f);
        if (m0 + r < n)
            xv = *(const float4*)(X + (size_t)(m0 + r) * 128 + k0 + q * 4);
        if (RELU) {
            xv.x = fmaxf(xv.x, 0.f); xv.y = fmaxf(xv.y, 0.f);
            xv.z = fmaxf(xv.z, 0.f); xv.w = fmaxf(xv.w, 0.f);
        }
        XsT[q * 4 + 0][r] = xv.x;
        XsT[q * 4 + 1][r] = xv.y;
        XsT[q * 4 + 2][r] = xv.z;
        XsT[q * 4 + 3][r] = xv.w;

        constexpr int F4 = 16 * TN / 4;
        #pragma unroll
        for (int s = 0; s < F4 / 256; s++) {
            int fv = tid + s * 256;
            int kk = fv / (TN / 4), c4 = fv % (TN / 4);
            *(float4*)&Ws[kk][c4 * 4] =
                *(const float4*)(W + (size_t)(k0 + kk) * TN + c4 * 4);
        }
        __syncthreads();

        #pragma unroll
        for (int kk = 0; kk < 16; kk++) {
            float a[4], b[CPT];
            #pragma unroll
            for (int i = 0; i < 4; i++) a[i] = XsT[kk][ty * 4 + i];
            #pragma unroll
            for (int j = 0; j < CPT; j++) b[j] = Ws[kk][tx * CPT + j];
            #pragma unroll
            for (int i = 0; i < 4; i++)
                #pragma unroll
                for (int j = 0; j < CPT; j++)
                    acc[i][j] = fmaf(a[i], b[j], acc[i][j]);
        }
        __syncthreads();
    }

    #pragma unroll
    for (int i = 0; i < 4; i++) {
        int row = m0 + ty * 4 + i;
        if (row < n) {
            float dv = g_dinv[row];
            #pragma unroll
            for (int j = 0; j < CPT; j++)
                out[(size_t)row * TN + tx * CPT + j] = acc[i][j] * dv;
        }
    }
}

// ---------------- pull aggregation: one warp per node ----------------
// out[i] = dinv[i] * (tmp[i] + sum_{e in in(i)} tmp[src_e]) + bias
template<int D>
__global__ void agg_k(const float* __restrict__ tmp, const float* __restrict__ bias,
                      float* __restrict__ out, int n) {
    int w = (blockIdx.x * blockDim.x + threadIdx.x) >> 5;
    if (w >= n) return;
    int l = threadIdx.x & 31;
    int s0 = g_rowptr[w], s1 = g_rowptr[w + 1];
    float dv = g_dinv[w];

    if (D == 128) {
        const float4* t = (const float4*)tmp;
        float4 acc = t[(size_t)w * 32 + l];       // self-loop term
        for (int j = s0; j < s1; j++) {
            int s = g_esrc[j];
            float4 v = t[(size_t)s * 32 + l];
            acc.x += v.x; acc.y += v.y; acc.z += v.z; acc.w += v.w;
        }
        float4 bb = ((const float4*)bias)[l];
        float4 o;
        o.x = fmaf(acc.x, dv, bb.x);
        o.y = fmaf(acc.y, dv, bb.y);
        o.z = fmaf(acc.z, dv, bb.z);
        o.w = fmaf(acc.w, dv, bb.w);
        ((float4*)out)[(size_t)w * 32 + l] = o;
    } else {  // D == 64
        const float2* t = (const float2*)tmp;
        float2 acc = t[(size_t)w * 32 + l];
        for (int j = s0; j < s1; j++) {
            int s = g_esrc[j];
            float2 v = t[(size_t)s * 32 + l];
            acc.x += v.x; acc.y += v.y;
        }
        float2 bb = ((const float2*)bias)[l];
        float2 o;
        o.x = fmaf(acc.x, dv, bb.x);
        o.y = fmaf(acc.y, dv, bb.y);
        ((float2*)out)[(size_t)w * 32 + l] = o;
    }
}

// ---------------- decode: out[p] = dot(z[a_p], z[b_p]) over 64 dims ----------------
__global__ void decode_k(const float* __restrict__ z, const void* eli,
                         float* __restrict__ out, int EL) {
    int w = (blockIdx.x * blockDim.x + threadIdx.x) >> 5;
    if (w >= EL) return;
    int l = threadIdx.x & 31;
    int is64 = g_is64;
    int a = eidx(eli, (size_t)w, is64);
    int b = eidx(eli, (size_t)EL + w, is64);
    const float2* z2 = (const float2*)z;
    float2 pa = z2[(size_t)a * 32 + l];
    float2 pb = z2[(size_t)b * 32 + l];
    float p = pa.x * pb.x + pa.y * pb.y;
    #pragma unroll
    for (int off = 16; off > 0; off >>= 1)
        p += __shfl_xor_sync(0xffffffffu, p, off);
    if (l == 0) out[w] = p;
}

// ---------------- launch ----------------
extern "C" void kernel_launch(void* const* d_in, const int* in_sizes, int n_in,
                              void* d_out, int out_size) {
    const float* x  = (const float*)d_in[0];
    const void*  ei = d_in[1];
    const void*  eli= d_in[2];
    const float* W1 = (const float*)d_in[3];
    const float* b1 = (const float*)d_in[4];
    const float* W2 = (const float*)d_in[5];
    const float* b2 = (const float*)d_in[6];
    const float* W3 = (const float*)d_in[7];
    const float* b3 = (const float*)d_in[8];
    float* out = (float*)d_out;

    int N  = in_sizes[0] / 128;
    int E  = in_sizes[1] / 2;
    int EL = in_sizes[2] / 2;

    float* A = g_bufA;  // device-global addresses are valid in device code;
    float* B = g_bufB;  // get them for host-side passing:
    cudaGetSymbolAddress((void**)&A, g_bufA);
    cudaGetSymbolAddress((void**)&B, g_bufB);

    int nb = (N + 511) / 512;

    detect_dtype_k<<<1, 256>>>(ei, N);
    zero_k<<<(N + 255) / 256, 256>>>(N);
    count_k<<<(E + 255) / 256, 256>>>(ei, E);
    scan1_k<<<nb, 512>>>(N);
    scan2_k<<<1, 512>>>(nb);
    scan3_k<<<nb, 512>>>(N, E);
    dinv_k<<<(N + 255) / 256, 256>>>(N);
    fill_k<<<(E + 255) / 256, 256>>>(ei, E);

    int gg = (N + 63) / 64;
    int ab = (N * 32 + 255) / 256;

    // Layer 1: A = (x @ W1) * dinv ; B = agg(A) + b1   (relu deferred)
    gemm_k<128, false><<<gg, 256>>>(x, W1, A, N);
    agg_k<128><<<ab, 256>>>(A, b1, B, N);
    // Layer 2: A = (relu(B) @ W2) * dinv ; B = agg(A) + b2
    gemm_k<128, true><<<gg, 256>>>(B, W2, A, N);
    agg_k<128><<<ab, 256>>>(A, b2, B, N);
    // Layer 3: A = (relu(B) @ W3) * dinv ; B = agg(A) + b3  (z, no relu)
    gemm_k<64, true><<<gg, 256>>>(B, W3, A, N);
    agg_k<64><<<ab, 256>>>(A, b3, B, N);

    decode_k<<<(EL * 32 + 255) / 256, 256>>>(B, eli, out, EL);
}

// round 3
// speedup vs baseline: 1.2578x; 1.2578x over previous
#include <cuda_runtime.h>
#include <cuda_bf16.h>
#include <stdint.h>

#define MAXN 100000
#define MAXE 1600000
#define MAXEL 200000

// ---------------- static scratch ----------------
__device__ float g_bufA[(size_t)MAXN * 128];
__device__ float g_bufB[(size_t)MAXN * 128];
__device__ float g_dinv[MAXN];
__device__ int   g_cnt[MAXN];
__device__ int   g_cur[MAXN];
__device__ int   g_rowptr[MAXN + 1];
__device__ int   g_bsum[512];
__device__ int   g_boff[512];
__device__ int   g_esrc[MAXE];
__device__ int   g_is64;

// ---------------- index dtype detection ----------------
__global__ void detect_dtype_k(const void* ei, int n) {
    __shared__ int ok;
    if (threadIdx.x == 0) ok = 1;
    __syncthreads();
    const long long* p = (const long long*)ei;
    for (int i = threadIdx.x; i < 1024; i += blockDim.x) {
        long long v = p[i];
        if (v < 0 || v >= (long long)n) ok = 0;
    }
    __syncthreads();
    if (threadIdx.x == 0) g_is64 = ok;
}

__device__ __forceinline__ int eidx(const void* p, size_t i, int is64) {
    return is64 ? (int)((const long long*)p)[i] : ((const int*)p)[i];
}

// ---------------- degree / CSR build ----------------
__global__ void zero_k(int n) {
    int i = blockIdx.x * blockDim.x + threadIdx.x;
    if (i < n) g_cnt[i] = 0;
}

__global__ void count_k(const void* ei, int E) {
    int e = blockIdx.x * blockDim.x + threadIdx.x;
    if (e >= E) return;
    int dst = eidx(ei, (size_t)E + e, g_is64);
    atomicAdd(&g_cnt[dst], 1);
}

__global__ void scan1_k(int n) {
    __shared__ int s[512];
    int t = threadIdx.x;
    int idx = blockIdx.x * 512 + t;
    int v = (idx < n) ? g_cnt[idx] : 0;
    s[t] = v;
    __syncthreads();
    #pragma unroll
    for (int off = 1; off < 512; off <<= 1) {
        int add = (t >= off) ? s[t - off] : 0;
        __syncthreads();
        s[t] += add;
        __syncthreads();
    }
    if (idx < n) g_rowptr[idx] = s[t] - v;
    if (t == 511) g_bsum[blockIdx.x] = s[511];
}

__global__ void scan2_k(int nb) {
    __shared__ int s[512];
    int t = threadIdx.x;
    int v = (t < nb) ? g_bsum[t] : 0;
    s[t] = v;
    __syncthreads();
    #pragma unroll
    for (int off = 1; off < 512; off <<= 1) {
        int add = (t >= off) ? s[t - off] : 0;
        __syncthreads();
        s[t] += add;
        __syncthreads();
    }
    g_boff[t] = s[t] - v;
}

__global__ void scan3_k(int n, int E) {
    int idx = blockIdx.x * 512 + threadIdx.x;
    if (idx < n) {
        int v = g_rowptr[idx] + g_boff[blockIdx.x];
        g_rowptr[idx] = v;
        g_cur[idx] = v;                 // fill cursor starts at row begin
    }
    if (idx == 0) g_rowptr[n] = E;
}

__global__ void dinv_k(int n) {
    int i = blockIdx.x * blockDim.x + threadIdx.x;
    if (i < n) g_dinv[i] = rsqrtf((float)g_cnt[i] + 1.0f);
}

__global__ void fill_k(const void* ei, int E) {
    int e = blockIdx.x * blockDim.x + threadIdx.x;
    if (e >= E) return;
    int is64 = g_is64;
    int src = eidx(ei, (size_t)e, is64);
    int dst = eidx(ei, (size_t)E + e, is64);
    int pos = atomicAdd(&g_cur[dst], 1);
    g_esrc[pos] = src;
}

// ---------------- GEMM: out[row] = relu?(X[row]) @ W * dinv[row] ----------------
// K = 128 fixed. Tile 128 x TN, 256 threads, per-thread 8 x (TN/16).
__device__ __forceinline__ void relu4(float4& v) {
    v.x = fmaxf(v.x, 0.f); v.y = fmaxf(v.y, 0.f);
    v.z = fmaxf(v.z, 0.f); v.w = fmaxf(v.w, 0.f);
}

template<int TN, bool RELU>
__global__ void __launch_bounds__(256, 2)
gemm2_k(const float* __restrict__ X, const float* __restrict__ W,
        float* __restrict__ out, int n) {
    constexpr int CPT = TN / 16;                 // 8 (TN=128) or 4 (TN=64)
    __shared__ float XsT[16][132];               // transposed X chunk [k][m]
    __shared__ float Ws[16][TN];
    int tid = threadIdx.x;
    int tx = tid & 15, ty = tid >> 4;
    int m0 = blockIdx.x * 128;

    // X loader: row lr, k-offset lk (8 consecutive k per thread = 2 float4)
    int lr = tid >> 1;
    int lk = (tid & 1) * 8;
    bool xok = (m0 + lr) < n;
    const float* xbase = X + (size_t)(m0 + lr) * 128 + lk;

    // W loader: row wk, CPT consecutive n per thread
    int wk = tid >> 4;
    int wn = (tid & 15) * CPT;
    const float* wbase = W + (size_t)wk * TN + wn;

    float4 xr0, xr1, wr0, wr1;
    const float4 z4 = make_float4(0.f, 0.f, 0.f, 0.f);

    float acc[8][CPT];
    #pragma unroll
    for (int i = 0; i < 8; i++)
        #pragma unroll
        for (int j = 0; j < CPT; j++) acc[i][j] = 0.f;

    // prefetch chunk 0
    xr0 = xok ? *(const float4*)(xbase + 0) : z4;
    xr1 = xok ? *(const float4*)(xbase + 4) : z4;
    if (RELU) { relu4(xr0); relu4(xr1); }
    wr0 = *(const float4*)(wbase);
    if (CPT == 8) wr1 = *(const float4*)(wbase + 4);

    #pragma unroll 1
    for (int c = 0; c < 8; c++) {
        // store prefetched chunk to smem
        XsT[lk + 0][lr] = xr0.x; XsT[lk + 1][lr] = xr0.y;
        XsT[lk + 2][lr] = xr0.z; XsT[lk + 3][lr] = xr0.w;
        XsT[lk + 4][lr] = xr1.x; XsT[lk + 5][lr] = xr1.y;
        XsT[lk + 6][lr] = xr1.z; XsT[lk + 7][lr] = xr1.w;
        *(float4*)&Ws[wk][wn] = wr0;
        if (CPT == 8) *(float4*)&Ws[wk][wn + 4] = wr1;
        __syncthreads();

        // prefetch next chunk from global
        if (c < 7) {
            int k0 = (c + 1) * 16;
            xr0 = xok ? *(const float4*)(xbase + k0) : z4;
            xr1 = xok ? *(const float4*)(xbase + k0 + 4) : z4;
            if (RELU) { relu4(xr0); relu4(xr1); }
            wr0 = *(const float4*)(wbase + (size_t)k0 * TN);
            if (CPT == 8) wr1 = *(const float4*)(wbase + (size_t)k0 * TN + 4);
        }

        // compute current chunk
        #pragma unroll
        for (int kk = 0; kk < 16; kk++) {
            float a[8], b[CPT];
            *(float4*)(a)     = *(const float4*)&XsT[kk][ty * 8];
            *(float4*)(a + 4) = *(const float4*)&XsT[kk][ty * 8 + 4];
            *(float4*)(b)     = *(const float4*)&Ws[kk][tx * CPT];
            if (CPT == 8) *(float4*)(b + 4) = *(const float4*)&Ws[kk][tx * CPT + 4];
            #pragma unroll
            for (int i = 0; i < 8; i++)
                #pragma unroll
                for (int j = 0; j < CPT; j++)
                    acc[i][j] = fmaf(a[i], b[j], acc[i][j]);
        }
        __syncthreads();
    }

    #pragma unroll
    for (int i = 0; i < 8; i++) {
        int row = m0 + ty * 8 + i;
        if (row < n) {
            float dv = g_dinv[row];
            float* o = out + (size_t)row * TN + tx * CPT;
            #pragma unroll
            for (int j4 = 0; j4 < CPT / 4; j4++) {
                float4 v;
                v.x = acc[i][j4 * 4 + 0] * dv;
                v.y = acc[i][j4 * 4 + 1] * dv;
                v.z = acc[i][j4 * 4 + 2] * dv;
                v.w = acc[i][j4 * 4 + 3] * dv;
                *(float4*)(o + j4 * 4) = v;
            }
        }
    }
}

// ---------------- pull aggregation: one warp per node ----------------
template<int D>
__global__ void agg_k(const float* __restrict__ tmp, const float* __restrict__ bias,
                      float* __restrict__ out, int n) {
    int w = (blockIdx.x * blockDim.x + threadIdx.x) >> 5;
    if (w >= n) return;
    int l = threadIdx.x & 31;
    int s0 = g_rowptr[w], s1 = g_rowptr[w + 1];
    float dv = g_dinv[w];

    if (D == 128) {
        const float4* t = (const float4*)tmp;
        float4 acc = t[(size_t)w * 32 + l];
        for (int j = s0; j < s1; j++) {
            int s = g_esrc[j];
            float4 v = t[(size_t)s * 32 + l];
            acc.x += v.x; acc.y += v.y; acc.z += v.z; acc.w += v.w;
        }
        float4 bb = ((const float4*)bias)[l];
        float4 o;
        o.x = fmaf(acc.x, dv, bb.x);
        o.y = fmaf(acc.y, dv, bb.y);
        o.z = fmaf(acc.z, dv, bb.z);
        o.w = fmaf(acc.w, dv, bb.w);
        ((float4*)out)[(size_t)w * 32 + l] = o;
    } else {
        const float2* t = (const float2*)tmp;
        float2 acc = t[(size_t)w * 32 + l];
        for (int j = s0; j < s1; j++) {
            int s = g_esrc[j];
            float2 v = t[(size_t)s * 32 + l];
            acc.x += v.x; acc.y += v.y;
        }
        float2 bb = ((const float2*)bias)[l];
        float2 o;
        o.x = fmaf(acc.x, dv, bb.x);
        o.y = fmaf(acc.y, dv, bb.y);
        ((float2*)out)[(size_t)w * 32 + l] = o;
    }
}

// ---------------- decode ----------------
__global__ void decode_k(const float* __restrict__ z, const void* eli,
                         float* __restrict__ out, int EL) {
    int w = (blockIdx.x * blockDim.x + threadIdx.x) >> 5;
    if (w >= EL) return;
    int l = threadIdx.x & 31;
    int is64 = g_is64;
    int a = eidx(eli, (size_t)w, is64);
    int b = eidx(eli, (size_t)EL + w, is64);
    const float2* z2 = (const float2*)z;
    float2 pa = z2[(size_t)a * 32 + l];
    float2 pb = z2[(size_t)b * 32 + l];
    float p = pa.x * pb.x + pa.y * pb.y;
    #pragma unroll
    for (int off = 16; off > 0; off >>= 1)
        p += __shfl_xor_sync(0xffffffffu, p, off);
    if (l == 0) out[w] = p;
}

// ---------------- launch ----------------
extern "C" void kernel_launch(void* const* d_in, const int* in_sizes, int n_in,
                              void* d_out, int out_size) {
    const float* x  = (const float*)d_in[0];
    const void*  ei = d_in[1];
    const void*  eli= d_in[2];
    const float* W1 = (const float*)d_in[3];
    const float* b1 = (const float*)d_in[4];
    const float* W2 = (const float*)d_in[5];
    const float* b2 = (const float*)d_in[6];
    const float* W3 = (const float*)d_in[7];
    const float* b3 = (const float*)d_in[8];
    float* out = (float*)d_out;

    int N  = in_sizes[0] / 128;
    int E  = in_sizes[1] / 2;
    int EL = in_sizes[2] / 2;

    float *A, *B;
    cudaGetSymbolAddress((void**)&A, g_bufA);
    cudaGetSymbolAddress((void**)&B, g_bufB);

    int nb = (N + 511) / 512;

    detect_dtype_k<<<1, 256>>>(ei, N);
    zero_k<<<(N + 255) / 256, 256>>>(N);
    count_k<<<(E + 255) / 256, 256>>>(ei, E);
    scan1_k<<<nb, 512>>>(N);
    scan2_k<<<1, 512>>>(nb);
    scan3_k<<<nb, 512>>>(N, E);
    dinv_k<<<(N + 255) / 256, 256>>>(N);
    fill_k<<<(E + 255) / 256, 256>>>(ei, E);

    int gg = (N + 127) / 128;
    int ab = (N * 32 + 255) / 256;

    gemm2_k<128, false><<<gg, 256>>>(x, W1, A, N);
    agg_k<128><<<ab, 256>>>(A, b1, B, N);
    gemm2_k<128, true><<<gg, 256>>>(B, W2, A, N);
    agg_k<128><<<ab, 256>>>(A, b2, B, N);
    gemm2_k<64, true><<<gg, 256>>>(B, W3, A, N);
    agg_k<64><<<ab, 256>>>(A, b3, B, N);

    decode_k<<<(EL * 32 + 255) / 256, 256>>>(B, eli, out, EL);
}

// round 5
// speedup vs baseline: 1.5198x; 1.2084x over previous
#include <cuda_runtime.h>
#include <cuda_bf16.h>
#include <stdint.h>

#define MAXN 100000
#define MAXE 1600000
#define MAXEL 200000

// ---------------- static scratch ----------------
__device__ float g_bufA[(size_t)MAXN * 128];
__device__ float g_bufB[(size_t)MAXN * 128];
__device__ float g_dinv[MAXN];
__device__ int   g_cnt[MAXN];
__device__ int   g_cur[MAXN];
__device__ int   g_rowptr[MAXN + 1];
__device__ int   g_bsum[512];
__device__ int   g_boff[512];
__device__ int   g_esrc[MAXE];
__device__ int   g_is64;
// pre-split weights in swizzled ldmatrix layout: [TN rows][128 k] bf16,
// row stride 256B, 16B-chunk c stored at (c ^ (row&7))
__device__ __nv_bfloat16 g_whi[128 * 128];
__device__ __nv_bfloat16 g_wlo[128 * 128];

// ---------------- helpers ----------------
__device__ __forceinline__ uint32_t smem_u32(const void* p) {
    uint32_t a;
    asm("{ .reg .u64 t; cvta.to.shared.u64 t, %1; cvt.u32.u64 %0, t; }" : "=r"(a) : "l"(p));
    return a;
}
__device__ __forceinline__ uint32_t pack2(float a, float b) {
    __nv_bfloat162 t = __floats2bfloat162_rn(a, b);
    return *reinterpret_cast<uint32_t*>(&t);
}
__device__ __forceinline__ void relu4(float4& v) {
    v.x = fmaxf(v.x, 0.f); v.y = fmaxf(v.y, 0.f);
    v.z = fmaxf(v.z, 0.f); v.w = fmaxf(v.w, 0.f);
}
__device__ __forceinline__ void ldsm_x4(uint32_t* r, uint32_t addr) {
    asm volatile("ldmatrix.sync.aligned.m8n8.x4.shared.b16 {%0,%1,%2,%3}, [%4];"
                 : "=r"(r[0]), "=r"(r[1]), "=r"(r[2]), "=r"(r[3]) : "r"(addr));
}
__device__ __forceinline__ void ldsm_x2(uint32_t* r, uint32_t addr) {
    asm volatile("ldmatrix.sync.aligned.m8n8.x2.shared.b16 {%0,%1}, [%2];"
                 : "=r"(r[0]), "=r"(r[1]) : "r"(addr));
}
__device__ __forceinline__ void mma_bf16(float* d, const uint32_t* a, const uint32_t* b) {
    asm volatile(
        "mma.sync.aligned.m16n8k16.row.col.f32.bf16.bf16.f32 "
        "{%0,%1,%2,%3}, {%4,%5,%6,%7}, {%8,%9}, {%0,%1,%2,%3};"
        : "+f"(d[0]), "+f"(d[1]), "+f"(d[2]), "+f"(d[3])
        : "r"(a[0]), "r"(a[1]), "r"(a[2]), "r"(a[3]), "r"(b[0]), "r"(b[1]));
}

// ---------------- index dtype detection ----------------
__global__ void detect_dtype_k(const void* ei, int n) {
    __shared__ int ok;
    if (threadIdx.x == 0) ok = 1;
    __syncthreads();
    const long long* p = (const long long*)ei;
    for (int i = threadIdx.x; i < 1024; i += blockDim.x) {
        long long v = p[i];
        if (v < 0 || v >= (long long)n) ok = 0;
    }
    __syncthreads();
    if (threadIdx.x == 0) g_is64 = ok;
}
__device__ __forceinline__ int eidx(const void* p, size_t i, int is64) {
    return is64 ? (int)((const long long*)p)[i] : ((const int*)p)[i];
}

// ---------------- degree / CSR build ----------------
__global__ void zero_k(int n) {
    int i = blockIdx.x * blockDim.x + threadIdx.x;
    if (i < n) g_cnt[i] = 0;
}
__global__ void count_k(const void* ei, int E) {
    int e = blockIdx.x * blockDim.x + threadIdx.x;
    if (e >= E) return;
    atomicAdd(&g_cnt[eidx(ei, (size_t)E + e, g_is64)], 1);
}
__global__ void scan1_k(int n) {
    __shared__ int s[512];
    int t = threadIdx.x, idx = blockIdx.x * 512 + t;
    int v = (idx < n) ? g_cnt[idx] : 0;
    s[t] = v;
    __syncthreads();
    #pragma unroll
    for (int off = 1; off < 512; off <<= 1) {
        int add = (t >= off) ? s[t - off] : 0;
        __syncthreads();
        s[t] += add;
        __syncthreads();
    }
    if (idx < n) g_rowptr[idx] = s[t] - v;
    if (t == 511) g_bsum[blockIdx.x] = s[511];
}
__global__ void scan2_k(int nb) {
    __shared__ int s[512];
    int t = threadIdx.x;
    int v = (t < nb) ? g_bsum[t] : 0;
    s[t] = v;
    __syncthreads();
    #pragma unroll
    for (int off = 1; off < 512; off <<= 1) {
        int add = (t >= off) ? s[t - off] : 0;
        __syncthreads();
        s[t] += add;
        __syncthreads();
    }
    g_boff[t] = s[t] - v;
}
__global__ void scan3_k(int n, int E) {
    int idx = blockIdx.x * 512 + threadIdx.x;
    if (idx < n) {
        int v = g_rowptr[idx] + g_boff[blockIdx.x];
        g_rowptr[idx] = v;
        g_cur[idx] = v;
    }
    if (idx == 0) g_rowptr[n] = E;
}
__global__ void dinv_k(int n) {
    int i = blockIdx.x * blockDim.x + threadIdx.x;
    if (i < n) g_dinv[i] = rsqrtf((float)g_cnt[i] + 1.0f);
}
__global__ void fill_k(const void* ei, int E) {
    int e = blockIdx.x * blockDim.x + threadIdx.x;
    if (e >= E) return;
    int is64 = g_is64;
    int src = eidx(ei, (size_t)e, is64);
    int dst = eidx(ei, (size_t)E + e, is64);
    g_esrc[atomicAdd(&g_cur[dst], 1)] = src;
}

// ---------------- W split: W[k][n] fp32 -> (hi,lo) bf16 swizzled [n][k] ----------------
template<int TN>
__global__ void wsplit_k(const float* __restrict__ W) {
    int idx = blockIdx.x * blockDim.x + threadIdx.x;
    if (idx >= 128 * TN) return;
    int k = idx / TN, nn = idx - k * TN;
    float v = W[idx];
    __nv_bfloat16 hi = __float2bfloat16_rn(v);
    __nv_bfloat16 lo = __float2bfloat16_rn(v - __bfloat162float(hi));
    int c = k >> 3;
    int off = nn * 256 + (((c ^ (nn & 7)) << 4) | ((k & 7) << 1));
    *(__nv_bfloat16*)((char*)g_whi + off) = hi;
    *(__nv_bfloat16*)((char*)g_wlo + off) = lo;
}

// ---------------- mma.sync GEMM: out[row] = relu?(X[row]) @ W * dinv[row] ----------------
// Split bf16: D = Ahi*Bhi + Ahi*Blo + Alo*Bhi, fp32 accum. M-tile 128, K=128, N=TN.
template<int TN, bool RELU>
__global__ void __launch_bounds__(256)
gemm_mma_k(const float* __restrict__ X, float* __restrict__ out, int n) {
    extern __shared__ char sm[];
    constexpr int NT = TN / 16;            // n-tiles (8 cols) per warp
    char* xhi = sm;                        // 128 rows * 256B
    char* xlo = sm + 32768;
    char* whi = sm + 65536;                // TN rows * 256B
    char* wlo = whi + TN * 256;

    int tid = threadIdx.x;
    int m0 = blockIdx.x * 128;

    // copy pre-split, pre-swizzled W into smem
    {
        const uint4* gh = (const uint4*)g_whi;
        const uint4* gl = (const uint4*)g_wlo;
        uint4* dh = (uint4*)whi;
        uint4* dl = (uint4*)wlo;
        #pragma unroll 4
        for (int i = tid; i < TN * 16; i += 256) { dh[i] = gh[i]; dl[i] = gl[i]; }
    }

    // load X rows, relu, split, store swizzled
    {
        int r = tid >> 1, h = tid & 1;
        int row = m0 + r;
        bool ok = row < n;
        const float4* xr = (const float4*)(X + (size_t)row * 128) + h * 16;
        const float4 z4 = make_float4(0.f, 0.f, 0.f, 0.f);
        #pragma unroll
        for (int j = 0; j < 8; j++) {
            float4 v0 = ok ? xr[j * 2] : z4;
            float4 v1 = ok ? xr[j * 2 + 1] : z4;
            if (RELU) { relu4(v0); relu4(v1); }
            uint4 hv, lv;
            hv.x = pack2(v0.x, v0.y); hv.y = pack2(v0.z, v0.w);
            hv.z = pack2(v1.x, v1.y); hv.w = pack2(v1.z, v1.w);
            __nv_bfloat162 h0 = *(__nv_bfloat162*)&hv.x;
            __nv_bfloat162 h1 = *(__nv_bfloat162*)&hv.y;
            __nv_bfloat162 h2 = *(__nv_bfloat162*)&hv.z;
            __nv_bfloat162 h3 = *(__nv_bfloat162*)&hv.w;
            lv.x = pack2(v0.x - __low2float(h0), v0.y - __high2float(h0));
            lv.y = pack2(v0.z - __low2float(h1), v0.w - __high2float(h1));
            lv.z = pack2(v1.x - __low2float(h2), v1.y - __high2float(h2));
            lv.w = pack2(v1.z - __low2float(h3), v1.w - __high2float(h3));
            int c = h * 8 + j;
            int off = r * 256 + ((c ^ (r & 7)) << 4);
            *(uint4*)(xhi + off) = hv;
            *(uint4*)(xlo + off) = lv;
        }
    }
    __syncthreads();

    int wrp = tid >> 5, lane = tid & 31;
    int wm = wrp & 3;                      // m group: rows wm*32..+31
    int wnb = (wrp >> 2) * (TN / 2);       // n base col

    uint32_t xhi_u = smem_u32(xhi), xlo_u = smem_u32(xlo);
    uint32_t whi_u = smem_u32(whi), wlo_u = smem_u32(wlo);

    // ldmatrix lane address components
    int a_row_in = ((lane >> 3) & 1) * 8 + (lane & 7);   // row within 16-row tile
    int a_kc = lane >> 4;                                // +chunk for k+8
    int b_row_in = lane & 7;                             // n-row within 8
    int b_kc = (lane >> 3) & 1;

    float acc[2][NT][4];
    #pragma unroll
    for (int i = 0; i < 2; i++)
        #pragma unroll
        for (int j = 0; j < NT; j++)
            #pragma unroll
            for (int q = 0; q < 4; q++) acc[i][j][q] = 0.f;

    #pragma unroll
    for (int k = 0; k < 8; k++) {
        int c0 = k * 2;
        uint32_t ahi[2][4], alo[2][4];
        #pragma unroll
        for (int mt = 0; mt < 2; mt++) {
            int rr = wm * 32 + mt * 16 + a_row_in;
            int cc = c0 + a_kc;
            uint32_t off = rr * 256 + (((cc ^ (rr & 7)) & 15) << 4);
            ldsm_x4(ahi[mt], xhi_u + off);
            ldsm_x4(alo[mt], xlo_u + off);
        }
        uint32_t bhi[NT][2], blo[NT][2];
        #pragma unroll
        for (int nt = 0; nt < NT; nt++) {
            int rr = wnb + nt * 8 + b_row_in;
            int cc = c0 + b_kc;
            uint32_t off = rr * 256 + (((cc ^ (rr & 7)) & 15) << 4);
            ldsm_x2(bhi[nt], whi_u + off);
            ldsm_x2(blo[nt], wlo_u + off);
        }
        #pragma unroll
        for (int mt = 0; mt < 2; mt++)
            #pragma unroll
            for (int nt = 0; nt < NT; nt++) {
                mma_bf16(acc[mt][nt], ahi[mt], bhi[nt]);
                mma_bf16(acc[mt][nt], ahi[mt], blo[nt]);
                mma_bf16(acc[mt][nt], alo[mt], bhi[nt]);
            }
    }

    // epilogue: scale by dinv[row], store fp32
    #pragma unroll
    for (int mt = 0; mt < 2; mt++) {
        int row0 = m0 + wm * 32 + mt * 16 + (lane >> 2);
        int row1 = row0 + 8;
        float dv0 = (row0 < n) ? g_dinv[row0] : 0.f;
        float dv1 = (row1 < n) ? g_dinv[row1] : 0.f;
        #pragma unroll
        for (int nt = 0; nt < NT; nt++) {
            int col = wnb + nt * 8 + (lane & 3) * 2;
            if (row0 < n) {
                float2 v0 = make_float2(acc[mt][nt][0] * dv0, acc[mt][nt][1] * dv0);
                *(float2*)(out + (size_t)row0 * TN + col) = v0;
            }
            if (row1 < n) {
                float2 v1 = make_float2(acc[mt][nt][2] * dv1, acc[mt][nt][3] * dv1);
                *(float2*)(out + (size_t)row1 * TN + col) = v1;
            }
        }
    }
}

// ---------------- pull aggregation ----------------
template<int D>
__global__ void agg_k(const float* __restrict__ tmp, const float* __restrict__ bias,
                      float* __restrict__ out, int n) {
    int w = (blockIdx.x * blockDim.x + threadIdx.x) >> 5;
    if (w >= n) return;
    int l = threadIdx.x & 31;
    int s0 = g_rowptr[w], s1 = g_rowptr[w + 1];
    float dv = g_dinv[w];
    if (D == 128) {
        const float4* t = (const float4*)tmp;
        float4 acc = t[(size_t)w * 32 + l];
        for (int j = s0; j < s1; j++) {
            float4 v = t[(size_t)g_esrc[j] * 32 + l];
            acc.x += v.x; acc.y += v.y; acc.z += v.z; acc.w += v.w;
        }
        float4 bb = ((const float4*)bias)[l];
        float4 o;
        o.x = fmaf(acc.x, dv, bb.x); o.y = fmaf(acc.y, dv, bb.y);
        o.z = fmaf(acc.z, dv, bb.z); o.w = fmaf(acc.w, dv, bb.w);
        ((float4*)out)[(size_t)w * 32 + l] = o;
    } else {
        const float2* t = (const float2*)tmp;
        float2 acc = t[(size_t)w * 32 + l];
        for (int j = s0; j < s1; j++) {
            float2 v = t[(size_t)g_esrc[j] * 32 + l];
            acc.x += v.x; acc.y += v.y;
        }
        float2 bb = ((const float2*)bias)[l];
        float2 o;
        o.x = fmaf(acc.x, dv, bb.x); o.y = fmaf(acc.y, dv, bb.y);
        ((float2*)out)[(size_t)w * 32 + l] = o;
    }
}

// ---------------- decode ----------------
__global__ void decode_k(const float* __restrict__ z, const void* eli,
                         float* __restrict__ out, int EL) {
    int w = (blockIdx.x * blockDim.x + threadIdx.x) >> 5;
    if (w >= EL) return;
    int l = threadIdx.x & 31;
    int is64 = g_is64;
    int a = eidx(eli, (size_t)w, is64);
    int b = eidx(eli, (size_t)EL + w, is64);
    const float2* z2 = (const float2*)z;
    float2 pa = z2[(size_t)a * 32 + l];
    float2 pb = z2[(size_t)b * 32 + l];
    float p = pa.x * pb.x + pa.y * pb.y;
    #pragma unroll
    for (int off = 16; off > 0; off >>= 1)
        p += __shfl_xor_sync(0xffffffffu, p, off);
    if (l == 0) out[w] = p;
}

// ---------------- launch ----------------
extern "C" void kernel_launch(void* const* d_in, const int* in_sizes, int n_in,
                              void* d_out, int out_size) {
    const float* x  = (const float*)d_in[0];
    const void*  ei = d_in[1];
    const void*  eli= d_in[2];
    const float* W1 = (const float*)d_in[3];
    const float* b1 = (const float*)d_in[4];
    const float* W2 = (const float*)d_in[5];
    const float* b2 = (const float*)d_in[6];
    const float* W3 = (const float*)d_in[7];
    const float* b3 = (const float*)d_in[8];
    float* out = (float*)d_out;

    int N  = in_sizes[0] / 128;
    int E  = in_sizes[1] / 2;
    int EL = in_sizes[2] / 2;

    float *A, *B;
    cudaGetSymbolAddress((void**)&A, g_bufA);
    cudaGetSymbolAddress((void**)&B, g_bufB);

    int smem128 = 65536 + 2 * 128 * 256;   // 131072
    int smem64  = 65536 + 2 * 64 * 256;    // 98304
    cudaFuncSetAttribute(gemm_mma_k<128, false>, cudaFuncAttributeMaxDynamicSharedMemorySize, smem128);
    cudaFuncSetAttribute(gemm_mma_k<128, true>,  cudaFuncAttributeMaxDynamicSharedMemorySize, smem128);
    cudaFuncSetAttribute(gemm_mma_k<64, true>,   cudaFuncAttributeMaxDynamicSharedMemorySize, smem64);

    int nb = (N + 511) / 512;

    detect_dtype_k<<<1, 256>>>(ei, N);
    zero_k<<<(N + 255) / 256, 256>>>(N);
    count_k<<<(E + 255) / 256, 256>>>(ei, E);
    scan1_k<<<nb, 512>>>(N);
    scan2_k<<<1, 512>>>(nb);
    scan3_k<<<nb, 512>>>(N, E);
    dinv_k<<<(N + 255) / 256, 256>>>(N);
    fill_k<<<(E + 255) / 256, 256>>>(ei, E);

    int gg = (N + 127) / 128;
    int ab = (N * 32 + 255) / 256;

    wsplit_k<128><<<(128 * 128 + 255) / 256, 256>>>(W1);
    gemm_mma_k<128, false><<<gg, 256, smem128>>>(x, A, N);
    agg_k<128><<<ab, 256>>>(A, b1, B, N);

    wsplit_k<128><<<(128 * 128 + 255) / 256, 256>>>(W2);
    gemm_mma_k<128, true><<<gg, 256, smem128>>>(B, A, N);
    agg_k<128><<<ab, 256>>>(A, b2, B, N);

    wsplit_k<64><<<(128 * 64 + 255) / 256, 256>>>(W3);
    gemm_mma_k<64, true><<<gg, 256, smem64>>>(B, A, N);
    agg_k<64><<<ab, 256>>>(A, b3, B, N);

    decode_k<<<(EL * 32 + 255) / 256, 256>>>(B, eli, out, EL);
}

// round 7
// speedup vs baseline: 1.5742x; 1.0358x over previous
#include <cuda_runtime.h>
#include <cuda_bf16.h>
#include <stdint.h>

#define MAXN 100000
#define MAXE 1600000
#define MAXEL 200000

// ---------------- static scratch ----------------
__device__ float g_bufA[(size_t)MAXN * 128];
__device__ float g_bufB[(size_t)MAXN * 128];
__device__ float g_dinv[MAXN];
__device__ int   g_cnt[MAXN];
__device__ int   g_cur[MAXN];
__device__ int   g_rowptr[MAXN + 1];
__device__ int   g_bsum[512];
__device__ int   g_boff[512];
__device__ int   g_esrc[MAXE];
__device__ int   g_is64;
// per-layer pre-split weights, swizzled ldmatrix layout: [TN rows][128 k] bf16,
// row stride 256B, 16B-chunk c stored at (c ^ (row&7)).  slots: {hi,lo} x 3 layers
__device__ __nv_bfloat16 g_w[6 * 128 * 128];

// ---------------- helpers ----------------
__device__ __forceinline__ uint32_t smem_u32(const void* p) {
    uint32_t a;
    asm("{ .reg .u64 t; cvta.to.shared.u64 t, %1; cvt.u32.u64 %0, t; }" : "=r"(a) : "l"(p));
    return a;
}
__device__ __forceinline__ uint32_t pack2(float a, float b) {
    __nv_bfloat162 t = __floats2bfloat162_rn(a, b);
    return *reinterpret_cast<uint32_t*>(&t);
}
__device__ __forceinline__ void relu4(float4& v) {
    v.x = fmaxf(v.x, 0.f); v.y = fmaxf(v.y, 0.f);
    v.z = fmaxf(v.z, 0.f); v.w = fmaxf(v.w, 0.f);
}
__device__ __forceinline__ void ldsm_x4(uint32_t* r, uint32_t addr) {
    asm volatile("ldmatrix.sync.aligned.m8n8.x4.shared.b16 {%0,%1,%2,%3}, [%4];"
                 : "=r"(r[0]), "=r"(r[1]), "=r"(r[2]), "=r"(r[3]) : "r"(addr));
}
__device__ __forceinline__ void mma_bf16(float* d, const uint32_t* a, const uint32_t* b) {
    asm volatile(
        "mma.sync.aligned.m16n8k16.row.col.f32.bf16.bf16.f32 "
        "{%0,%1,%2,%3}, {%4,%5,%6,%7}, {%8,%9}, {%0,%1,%2,%3};"
        : "+f"(d[0]), "+f"(d[1]), "+f"(d[2]), "+f"(d[3])
        : "r"(a[0]), "r"(a[1]), "r"(a[2]), "r"(a[3]), "r"(b[0]), "r"(b[1]));
}
__device__ __forceinline__ int eidx(const void* p, size_t i, int is64) {
    return is64 ? (int)((const long long*)p)[i] : ((const int*)p)[i];
}

// ---------------- preproc: detect dtype + zero counts ----------------
__global__ void init_k(const void* ei, int n) {
    int i = blockIdx.x * blockDim.x + threadIdx.x;
    if (i < n) g_cnt[i] = 0;
    if (blockIdx.x == 0) {
        __shared__ int ok;
        if (threadIdx.x == 0) ok = 1;
        __syncthreads();
        const long long* p = (const long long*)ei;
        for (int j = threadIdx.x; j < 1024; j += blockDim.x) {
            long long v = p[j];
            if (v < 0 || v >= (long long)n) ok = 0;
        }
        __syncthreads();
        if (threadIdx.x == 0) g_is64 = ok;
    }
}
__global__ void count_k(const void* ei, int E) {
    int e = blockIdx.x * blockDim.x + threadIdx.x;
    if (e >= E) return;
    atomicAdd(&g_cnt[eidx(ei, (size_t)E + e, g_is64)], 1);
}
__global__ void scan1_k(int n) {
    __shared__ int s[512];
    int t = threadIdx.x, idx = blockIdx.x * 512 + t;
    int v = (idx < n) ? g_cnt[idx] : 0;
    s[t] = v;
    __syncthreads();
    #pragma unroll
    for (int off = 1; off < 512; off <<= 1) {
        int add = (t >= off) ? s[t - off] : 0;
        __syncthreads();
        s[t] += add;
        __syncthreads();
    }
    if (idx < n) g_rowptr[idx] = s[t] - v;
    if (t == 511) g_bsum[blockIdx.x] = s[511];
}
__global__ void scan2_k(int nb) {
    __shared__ int s[512];
    int t = threadIdx.x;
    int v = (t < nb) ? g_bsum[t] : 0;
    s[t] = v;
    __syncthreads();
    #pragma unroll
    for (int off = 1; off < 512; off <<= 1) {
        int add = (t >= off) ? s[t - off] : 0;
        __syncthreads();
        s[t] += add;
        __syncthreads();
    }
    g_boff[t] = s[t] - v;
}
__global__ void scan3_k(int n, int E) {   // + dinv + fill cursor
    int idx = blockIdx.x * 512 + threadIdx.x;
    if (idx < n) {
        int v = g_rowptr[idx] + g_boff[blockIdx.x];
        g_rowptr[idx] = v;
        g_cur[idx] = v;
        g_dinv[idx] = rsqrtf((float)g_cnt[idx] + 1.0f);
    }
    if (idx == 0) g_rowptr[n] = E;
}
__global__ void fill_k(const void* ei, int E) {
    int e = blockIdx.x * blockDim.x + threadIdx.x;
    if (e >= E) return;
    int is64 = g_is64;
    int src = eidx(ei, (size_t)e, is64);
    int dst = eidx(ei, (size_t)E + e, is64);
    g_esrc[atomicAdd(&g_cur[dst], 1)] = src;
}

// ---------------- W split: W[k][n] fp32 -> (hi,lo) bf16 swizzled [n][k] ----------------
template<int TN>
__global__ void wsplit_k(const float* __restrict__ W, __nv_bfloat16* __restrict__ whi,
                         __nv_bfloat16* __restrict__ wlo) {
    int idx = blockIdx.x * blockDim.x + threadIdx.x;
    if (idx >= 128 * TN) return;
    int k = idx / TN, nn = idx - k * TN;
    float v = W[idx];
    __nv_bfloat16 hi = __float2bfloat16_rn(v);
    __nv_bfloat16 lo = __float2bfloat16_rn(v - __bfloat162float(hi));
    int c = k >> 3;
    int off = nn * 256 + (((c ^ (nn & 7)) << 4) | ((k & 7) << 1));
    *(__nv_bfloat16*)((char*)whi + off) = hi;
    *(__nv_bfloat16*)((char*)wlo + off) = lo;
}

// ---------------- mma.sync GEMM ----------------
// out[row] = relu?(X[row]) @ W  (* dinv[row] if SCALE).  M-tile 128, K=128, N=TN.
template<int TN, bool RELU, bool SCALE>
__global__ void __launch_bounds__(256)
gemm_mma_k(const float* __restrict__ X, float* __restrict__ out, int n,
           const __nv_bfloat16* __restrict__ gwhi, const __nv_bfloat16* __restrict__ gwlo) {
    extern __shared__ char sm[];
    constexpr int NT = TN / 16;
    char* xhi = sm;
    char* xlo = sm + 32768;
    char* whi = sm + 65536;
    char* wlo = whi + TN * 256;

    int tid = threadIdx.x;
    int m0 = blockIdx.x * 128;

    {
        const uint4* gh = (const uint4*)gwhi;
        const uint4* gl = (const uint4*)gwlo;
        uint4* dh = (uint4*)whi;
        uint4* dl = (uint4*)wlo;
        #pragma unroll 4
        for (int i = tid; i < TN * 16; i += 256) { dh[i] = gh[i]; dl[i] = gl[i]; }
    }

    {
        int r = tid >> 1, h = tid & 1;
        int row = m0 + r;
        bool ok = row < n;
        const float4* xr = (const float4*)(X + (size_t)row * 128) + h * 16;
        const float4 z4 = make_float4(0.f, 0.f, 0.f, 0.f);
        #pragma unroll
        for (int j = 0; j < 8; j++) {
            float4 v0 = ok ? xr[j * 2] : z4;
            float4 v1 = ok ? xr[j * 2 + 1] : z4;
            if (RELU) { relu4(v0); relu4(v1); }
            uint4 hv, lv;
            hv.x = pack2(v0.x, v0.y); hv.y = pack2(v0.z, v0.w);
            hv.z = pack2(v1.x, v1.y); hv.w = pack2(v1.z, v1.w);
            __nv_bfloat162 h0 = *(__nv_bfloat162*)&hv.x;
            __nv_bfloat162 h1 = *(__nv_bfloat162*)&hv.y;
            __nv_bfloat162 h2 = *(__nv_bfloat162*)&hv.z;
            __nv_bfloat162 h3 = *(__nv_bfloat162*)&hv.w;
            lv.x = pack2(v0.x - __low2float(h0), v0.y - __high2float(h0));
            lv.y = pack2(v0.z - __low2float(h1), v0.w - __high2float(h1));
            lv.z = pack2(v1.x - __low2float(h2), v1.y - __high2float(h2));
            lv.w = pack2(v1.z - __low2float(h3), v1.w - __high2float(h3));
            int c = h * 8 + j;
            int off = r * 256 + ((c ^ (r & 7)) << 4);
            *(uint4*)(xhi + off) = hv;
            *(uint4*)(xlo + off) = lv;
        }
    }
    __syncthreads();

    int wrp = tid >> 5, lane = tid & 31;
    int wm = wrp & 3;
    int wnb = (wrp >> 2) * (TN / 2);

    uint32_t xhi_u = smem_u32(xhi), xlo_u = smem_u32(xlo);
    uint32_t whi_u = smem_u32(whi), wlo_u = smem_u32(wlo);

    int a_row_in = ((lane >> 3) & 1) * 8 + (lane & 7);
    int a_kc = lane >> 4;
    int b_row_in = ((lane >> 4) << 3) + (lane & 7);   // pair-of-8-col-groups rows
    int b_kc = (lane >> 3) & 1;

    float acc[2][NT][4];
    #pragma unroll
    for (int i = 0; i < 2; i++)
        #pragma unroll
        for (int j = 0; j < NT; j++)
            #pragma unroll
            for (int q = 0; q < 4; q++) acc[i][j][q] = 0.f;

    #pragma unroll
    for (int k = 0; k < 8; k++) {
        int c0 = k * 2;
        uint32_t ahi[2][4], alo[2][4];
        #pragma unroll
        for (int mt = 0; mt < 2; mt++) {
            int rr = wm * 32 + mt * 16 + a_row_in;
            int cc = c0 + a_kc;
            uint32_t off = rr * 256 + (((cc ^ (rr & 7)) & 15) << 4);
            ldsm_x4(ahi[mt], xhi_u + off);
            ldsm_x4(alo[mt], xlo_u + off);
        }
        uint32_t bhi[NT][2], blo[NT][2];
        #pragma unroll
        for (int nt = 0; nt < NT; nt += 2) {
            int rr = wnb + nt * 8 + b_row_in;
            int cc = c0 + b_kc;
            uint32_t off = rr * 256 + (((cc ^ (rr & 7)) & 15) << 4);
            uint32_t t[4];
            ldsm_x4(t, whi_u + off);
            bhi[nt][0] = t[0]; bhi[nt][1] = t[1];
            bhi[nt + 1][0] = t[2]; bhi[nt + 1][1] = t[3];
            ldsm_x4(t, wlo_u + off);
            blo[nt][0] = t[0]; blo[nt][1] = t[1];
            blo[nt + 1][0] = t[2]; blo[nt + 1][1] = t[3];
        }
        #pragma unroll
        for (int mt = 0; mt < 2; mt++)
            #pragma unroll
            for (int nt = 0; nt < NT; nt++) {
                mma_bf16(acc[mt][nt], ahi[mt], bhi[nt]);
                mma_bf16(acc[mt][nt], ahi[mt], blo[nt]);
                mma_bf16(acc[mt][nt], alo[mt], bhi[nt]);
            }
    }

    #pragma unroll
    for (int mt = 0; mt < 2; mt++) {
        int row0 = m0 + wm * 32 + mt * 16 + (lane >> 2);
        int row1 = row0 + 8;
        float dv0 = 1.f, dv1 = 1.f;
        if (SCALE) {
            dv0 = (row0 < n) ? g_dinv[row0] : 0.f;
            dv1 = (row1 < n) ? g_dinv[row1] : 0.f;
        }
        #pragma unroll
        for (int nt = 0; nt < NT; nt++) {
            int col = wnb + nt * 8 + (lane & 3) * 2;
            if (row0 < n) {
                float2 v0 = make_float2(acc[mt][nt][0] * dv0, acc[mt][nt][1] * dv0);
                *(float2*)(out + (size_t)row0 * TN + col) = v0;
            }
            if (row1 < n) {
                float2 v1 = make_float2(acc[mt][nt][2] * dv1, acc[mt][nt][3] * dv1);
                *(float2*)(out + (size_t)row1 * TN + col) = v1;
            }
        }
    }
}

// ---------------- pull aggregation ----------------
// SRCSCALE=false: out[i] = dinv[i]*(T[i] + sum T[s]) + b   (T already *dinv)
// SRCSCALE=true : out[i] = dinv[i]*(dinv[i]*T[i] + sum dinv[s]*T[s]) + b
template<int D, bool SRCSCALE>
__global__ void agg_k(const float* __restrict__ tmp, const float* __restrict__ bias,
                      float* __restrict__ out, int n) {
    int w = (blockIdx.x * blockDim.x + threadIdx.x) >> 5;
    if (w >= n) return;
    int l = threadIdx.x & 31;
    int s0 = g_rowptr[w], s1 = g_rowptr[w + 1];
    float dv = g_dinv[w];
    if (D == 128) {
        const float4* t = (const float4*)tmp;
        float4 sv = t[(size_t)w * 32 + l];
        float4 acc;
        if (SRCSCALE) {
            acc.x = sv.x * dv; acc.y = sv.y * dv; acc.z = sv.z * dv; acc.w = sv.w * dv;
        } else acc = sv;
        for (int j = s0; j < s1; j++) {
            int s = g_esrc[j];
            float4 v = t[(size_t)s * 32 + l];
            if (SRCSCALE) {
                float ds = g_dinv[s];
                acc.x = fmaf(v.x, ds, acc.x); acc.y = fmaf(v.y, ds, acc.y);
                acc.z = fmaf(v.z, ds, acc.z); acc.w = fmaf(v.w, ds, acc.w);
            } else {
                acc.x += v.x; acc.y += v.y; acc.z += v.z; acc.w += v.w;
            }
        }
        float4 bb = ((const float4*)bias)[l];
        float4 o;
        o.x = fmaf(acc.x, dv, bb.x); o.y = fmaf(acc.y, dv, bb.y);
        o.z = fmaf(acc.z, dv, bb.z); o.w = fmaf(acc.w, dv, bb.w);
        ((float4*)out)[(size_t)w * 32 + l] = o;
    } else {
        const float2* t = (const float2*)tmp;
        float2 acc = t[(size_t)w * 32 + l];
        for (int j = s0; j < s1; j++) {
            float2 v = t[(size_t)g_esrc[j] * 32 + l];
            acc.x += v.x; acc.y += v.y;
        }
        float2 bb = ((const float2*)bias)[l];
        float2 o;
        o.x = fmaf(acc.x, dv, bb.x); o.y = fmaf(acc.y, dv, bb.y);
        ((float2*)out)[(size_t)w * 32 + l] = o;
    }
}

// ---------------- decode ----------------
__global__ void decode_k(const float* __restrict__ z, const void* eli,
                         float* __restrict__ out, int EL) {
    int w = (blockIdx.x * blockDim.x + threadIdx.x) >> 5;
    if (w >= EL) return;
    int l = threadIdx.x & 31;
    int is64 = g_is64;
    int a = eidx(eli, (size_t)w, is64);
    int b = eidx(eli, (size_t)EL + w, is64);
    const float2* z2 = (const float2*)z;
    float2 pa = z2[(size_t)a * 32 + l];
    float2 pb = z2[(size_t)b * 32 + l];
    float p = pa.x * pb.x + pa.y * pb.y;
    #pragma unroll
    for (int off = 16; off > 0; off >>= 1)
        p += __shfl_xor_sync(0xffffffffu, p, off);
    if (l == 0) out[w] = p;
}

// ---------------- launch ----------------
extern "C" void kernel_launch(void* const* d_in, const int* in_sizes, int n_in,
                              void* d_out, int out_size) {
    const float* x  = (const float*)d_in[0];
    const void*  ei = d_in[1];
    const void*  eli= d_in[2];
    const float* W1 = (const float*)d_in[3];
    const float* b1 = (const float*)d_in[4];
    const float* W2 = (const float*)d_in[5];
    const float* b2 = (const float*)d_in[6];
    const float* W3 = (const float*)d_in[7];
    const float* b3 = (const float*)d_in[8];
    float* out = (float*)d_out;

    int N  = in_sizes[0] / 128;
    int E  = in_sizes[1] / 2;
    int EL = in_sizes[2] / 2;

    float *A, *B;
    cudaGetSymbolAddress((void**)&A, g_bufA);
    cudaGetSymbolAddress((void**)&B, g_bufB);
    __nv_bfloat16* wbase;
    cudaGetSymbolAddress((void**)&wbase, g_w);
    __nv_bfloat16* w1h = wbase;             __nv_bfloat16* w1l = wbase + 1 * 16384;
    __nv_bfloat16* w2h = wbase + 2 * 16384; __nv_bfloat16* w2l = wbase + 3 * 16384;
    __nv_bfloat16* w3h = wbase + 4 * 16384; __nv_bfloat16* w3l = wbase + 5 * 16384;

    static cudaStream_t s2 = nullptr;
    static cudaEvent_t evF = nullptr, evJ = nullptr;
    if (!s2) {
        cudaStreamCreateWithFlags(&s2, cudaStreamNonBlocking);
        cudaEventCreateWithFlags(&evF, cudaEventDisableTiming);
        cudaEventCreateWithFlags(&evJ, cudaEventDisableTiming);
    }

    int smem128 = 65536 + 2 * 128 * 256;
    int smem64  = 65536 + 2 * 64 * 256;
    cudaFuncSetAttribute(gemm_mma_k<128, false, false>, cudaFuncAttributeMaxDynamicSharedMemorySize, smem128);
    cudaFuncSetAttribute(gemm_mma_k<128, true,  true>,  cudaFuncAttributeMaxDynamicSharedMemorySize, smem128);
    cudaFuncSetAttribute(gemm_mma_k<64,  true,  true>,  cudaFuncAttributeMaxDynamicSharedMemorySize, smem64);

    int nb = (N + 511) / 512;
    int gg = (N + 127) / 128;
    int ab = (N * 32 + 255) / 256;

    // fork: preprocessing on s2
    cudaEventRecord(evF, 0);
    cudaStreamWaitEvent(s2, evF, 0);
    init_k<<<(N + 255) / 256, 256, 0, s2>>>(ei, N);
    count_k<<<(E + 255) / 256, 256, 0, s2>>>(ei, E);
    scan1_k<<<nb, 512, 0, s2>>>(N);
    scan2_k<<<1, 512, 0, s2>>>(nb);
    scan3_k<<<nb, 512, 0, s2>>>(N, E);
    fill_k<<<(E + 255) / 256, 256, 0, s2>>>(ei, E);
    cudaEventRecord(evJ, s2);

    // main: weight splits + layer-1 GEMM (independent of preprocessing)
    wsplit_k<128><<<(128 * 128 + 255) / 256, 256>>>(W1, w1h, w1l);
    wsplit_k<128><<<(128 * 128 + 255) / 256, 256>>>(W2, w2h, w2l);
    wsplit_k<64><<<(128 * 64 + 255) / 256, 256>>>(W3, w3h, w3l);
    gemm_mma_k<128, false, false><<<gg, 256, smem128>>>(x, A, N, w1h, w1l);

    // join before aggregation
    cudaStreamWaitEvent(0, evJ, 0);

    agg_k<128, true><<<ab, 256>>>(A, b1, B, N);
    gemm_mma_k<128, true, true><<<gg, 256, smem128>>>(B, A, N, w2h, w2l);
    agg_k<128, false><<<ab, 256>>>(A, b2, B, N);
    gemm_mma_k<64, true, true><<<gg, 256, smem64>>>(B, A, N, w3h, w3l);
    agg_k<64, false><<<ab, 256>>>(A, b3, B, N);

    decode_k<<<(EL * 32 + 255) / 256, 256>>>(B, eli, out, EL);
}

// round 8
// speedup vs baseline: 1.5876x; 1.0085x over previous
#include <cuda_runtime.h>
#include <cuda_bf16.h>
#include <stdint.h>

#define MAXN 100000
#define MAXE 1600000
#define MAXEL 200000

// ---------------- static scratch ----------------
__device__ float g_bufA[(size_t)MAXN * 128];
__device__ float g_bufB[(size_t)MAXN * 128];
__device__ float g_dinv[MAXN];
__device__ int   g_cnt[MAXN];
__device__ int   g_cur[MAXN];
__device__ int   g_rowptr[MAXN + 1];
__device__ int   g_bsum[512];
__device__ int   g_boff[512];
__device__ int   g_esrc[MAXE];
__device__ int   g_is64;
// per-layer pre-split weights, swizzled ldmatrix layout: [TN rows][128 k] bf16,
// row stride 256B, 16B-chunk c stored at (c ^ (row&7)).  slots: {hi,lo} x 3 layers
__device__ __nv_bfloat16 g_w[6 * 128 * 128];

// ---------------- helpers ----------------
__device__ __forceinline__ uint32_t smem_u32(const void* p) {
    uint32_t a;
    asm("{ .reg .u64 t; cvta.to.shared.u64 t, %1; cvt.u32.u64 %0, t; }" : "=r"(a) : "l"(p));
    return a;
}
__device__ __forceinline__ uint32_t pack2(float a, float b) {
    __nv_bfloat162 t = __floats2bfloat162_rn(a, b);
    return *reinterpret_cast<uint32_t*>(&t);
}
__device__ __forceinline__ void relu4(float4& v) {
    v.x = fmaxf(v.x, 0.f); v.y = fmaxf(v.y, 0.f);
    v.z = fmaxf(v.z, 0.f); v.w = fmaxf(v.w, 0.f);
}
__device__ __forceinline__ void ldsm_x4(uint32_t* r, uint32_t addr) {
    asm volatile("ldmatrix.sync.aligned.m8n8.x4.shared.b16 {%0,%1,%2,%3}, [%4];"
                 : "=r"(r[0]), "=r"(r[1]), "=r"(r[2]), "=r"(r[3]) : "r"(addr));
}
__device__ __forceinline__ void mma_bf16(float* d, const uint32_t* a, const uint32_t* b) {
    asm volatile(
        "mma.sync.aligned.m16n8k16.row.col.f32.bf16.bf16.f32 "
        "{%0,%1,%2,%3}, {%4,%5,%6,%7}, {%8,%9}, {%0,%1,%2,%3};"
        : "+f"(d[0]), "+f"(d[1]), "+f"(d[2]), "+f"(d[3])
        : "r"(a[0]), "r"(a[1]), "r"(a[2]), "r"(a[3]), "r"(b[0]), "r"(b[1]));
}
__device__ __forceinline__ int eidx(const void* p, size_t i, int is64) {
    return is64 ? (int)((const long long*)p)[i] : ((const int*)p)[i];
}

// ---------------- preproc ----------------
__global__ void init_k(const void* ei, int n) {
    int i = blockIdx.x * blockDim.x + threadIdx.x;
    if (i < n) g_cnt[i] = 0;
    if (blockIdx.x == 0) {
        __shared__ int ok;
        if (threadIdx.x == 0) ok = 1;
        __syncthreads();
        const long long* p = (const long long*)ei;
        for (int j = threadIdx.x; j < 1024; j += blockDim.x) {
            long long v = p[j];
            if (v < 0 || v >= (long long)n) ok = 0;
        }
        __syncthreads();
        if (threadIdx.x == 0) g_is64 = ok;
    }
}
__global__ void count_k(const void* ei, int E) {
    int e = blockIdx.x * blockDim.x + threadIdx.x;
    if (e >= E) return;
    atomicAdd(&g_cnt[eidx(ei, (size_t)E + e, g_is64)], 1);
}
__global__ void scan1_k(int n) {
    __shared__ int s[512];
    int t = threadIdx.x, idx = blockIdx.x * 512 + t;
    int v = (idx < n) ? g_cnt[idx] : 0;
    s[t] = v;
    __syncthreads();
    #pragma unroll
    for (int off = 1; off < 512; off <<= 1) {
        int add = (t >= off) ? s[t - off] : 0;
        __syncthreads();
        s[t] += add;
        __syncthreads();
    }
    if (idx < n) g_rowptr[idx] = s[t] - v;
    if (t == 511) g_bsum[blockIdx.x] = s[511];
}
__global__ void scan2_k(int nb) {
    __shared__ int s[512];
    int t = threadIdx.x;
    int v = (t < nb) ? g_bsum[t] : 0;
    s[t] = v;
    __syncthreads();
    #pragma unroll
    for (int off = 1; off < 512; off <<= 1) {
        int add = (t >= off) ? s[t - off] : 0;
        __syncthreads();
        s[t] += add;
        __syncthreads();
    }
    g_boff[t] = s[t] - v;
}
__global__ void scan3_k(int n, int E) {   // + dinv + fill cursor
    int idx = blockIdx.x * 512 + threadIdx.x;
    if (idx < n) {
        int v = g_rowptr[idx] + g_boff[blockIdx.x];
        g_rowptr[idx] = v;
        g_cur[idx] = v;
        g_dinv[idx] = rsqrtf((float)g_cnt[idx] + 1.0f);
    }
    if (idx == 0) g_rowptr[n] = E;
}
__global__ void fill_k(const void* ei, int E) {
    int e = blockIdx.x * blockDim.x + threadIdx.x;
    if (e >= E) return;
    int is64 = g_is64;
    int src = eidx(ei, (size_t)e, is64);
    int dst = eidx(ei, (size_t)E + e, is64);
    g_esrc[atomicAdd(&g_cur[dst], 1)] = src;
}

// ---------------- W split ----------------
template<int TN>
__global__ void wsplit_k(const float* __restrict__ W, __nv_bfloat16* __restrict__ whi,
                         __nv_bfloat16* __restrict__ wlo) {
    int idx = blockIdx.x * blockDim.x + threadIdx.x;
    if (idx >= 128 * TN) return;
    int k = idx / TN, nn = idx - k * TN;
    float v = W[idx];
    __nv_bfloat16 hi = __float2bfloat16_rn(v);
    __nv_bfloat16 lo = __float2bfloat16_rn(v - __bfloat162float(hi));
    int c = k >> 3;
    int off = nn * 256 + (((c ^ (nn & 7)) << 4) | ((k & 7) << 1));
    *(__nv_bfloat16*)((char*)whi + off) = hi;
    *(__nv_bfloat16*)((char*)wlo + off) = lo;
}

// ---------------- mma.sync GEMM (row range [r0, n)) ----------------
template<int TN, bool RELU, bool SCALE>
__global__ void __launch_bounds__(256)
gemm_mma_k(const float* __restrict__ X, float* __restrict__ out, int r0, int n,
           const __nv_bfloat16* __restrict__ gwhi, const __nv_bfloat16* __restrict__ gwlo) {
    extern __shared__ char sm[];
    constexpr int NT = TN / 16;
    char* xhi = sm;
    char* xlo = sm + 32768;
    char* whi = sm + 65536;
    char* wlo = whi + TN * 256;

    int tid = threadIdx.x;
    int m0 = r0 + blockIdx.x * 128;

    {
        const uint4* gh = (const uint4*)gwhi;
        const uint4* gl = (const uint4*)gwlo;
        uint4* dh = (uint4*)whi;
        uint4* dl = (uint4*)wlo;
        #pragma unroll 4
        for (int i = tid; i < TN * 16; i += 256) { dh[i] = gh[i]; dl[i] = gl[i]; }
    }

    {
        int r = tid >> 1, h = tid & 1;
        int row = m0 + r;
        bool ok = row < n;
        const float4* xr = (const float4*)(X + (size_t)row * 128) + h * 16;
        const float4 z4 = make_float4(0.f, 0.f, 0.f, 0.f);
        #pragma unroll
        for (int j = 0; j < 8; j++) {
            float4 v0 = ok ? xr[j * 2] : z4;
            float4 v1 = ok ? xr[j * 2 + 1] : z4;
            if (RELU) { relu4(v0); relu4(v1); }
            uint4 hv, lv;
            hv.x = pack2(v0.x, v0.y); hv.y = pack2(v0.z, v0.w);
            hv.z = pack2(v1.x, v1.y); hv.w = pack2(v1.z, v1.w);
            __nv_bfloat162 h0 = *(__nv_bfloat162*)&hv.x;
            __nv_bfloat162 h1 = *(__nv_bfloat162*)&hv.y;
            __nv_bfloat162 h2 = *(__nv_bfloat162*)&hv.z;
            __nv_bfloat162 h3 = *(__nv_bfloat162*)&hv.w;
            lv.x = pack2(v0.x - __low2float(h0), v0.y - __high2float(h0));
            lv.y = pack2(v0.z - __low2float(h1), v0.w - __high2float(h1));
            lv.z = pack2(v1.x - __low2float(h2), v1.y - __high2float(h2));
            lv.w = pack2(v1.z - __low2float(h3), v1.w - __high2float(h3));
            int c = h * 8 + j;
            int off = r * 256 + ((c ^ (r & 7)) << 4);
            *(uint4*)(xhi + off) = hv;
            *(uint4*)(xlo + off) = lv;
        }
    }
    __syncthreads();

    int wrp = tid >> 5, lane = tid & 31;
    int wm = wrp & 3;
    int wnb = (wrp >> 2) * (TN / 2);

    uint32_t xhi_u = smem_u32(xhi), xlo_u = smem_u32(xlo);
    uint32_t whi_u = smem_u32(whi), wlo_u = smem_u32(wlo);

    int a_row_in = ((lane >> 3) & 1) * 8 + (lane & 7);
    int a_kc = lane >> 4;
    int b_row_in = ((lane >> 4) << 3) + (lane & 7);
    int b_kc = (lane >> 3) & 1;

    float acc[2][NT][4];
    #pragma unroll
    for (int i = 0; i < 2; i++)
        #pragma unroll
        for (int j = 0; j < NT; j++)
            #pragma unroll
            for (int q = 0; q < 4; q++) acc[i][j][q] = 0.f;

    #pragma unroll
    for (int k = 0; k < 8; k++) {
        int c0 = k * 2;
        uint32_t ahi[2][4], alo[2][4];
        #pragma unroll
        for (int mt = 0; mt < 2; mt++) {
            int rr = wm * 32 + mt * 16 + a_row_in;
            int cc = c0 + a_kc;
            uint32_t off = rr * 256 + (((cc ^ (rr & 7)) & 15) << 4);
            ldsm_x4(ahi[mt], xhi_u + off);
            ldsm_x4(alo[mt], xlo_u + off);
        }
        uint32_t bhi[NT][2], blo[NT][2];
        #pragma unroll
        for (int nt = 0; nt < NT; nt += 2) {
            int rr = wnb + nt * 8 + b_row_in;
            int cc = c0 + b_kc;
            uint32_t off = rr * 256 + (((cc ^ (rr & 7)) & 15) << 4);
            uint32_t t[4];
            ldsm_x4(t, whi_u + off);
            bhi[nt][0] = t[0]; bhi[nt][1] = t[1];
            bhi[nt + 1][0] = t[2]; bhi[nt + 1][1] = t[3];
            ldsm_x4(t, wlo_u + off);
            blo[nt][0] = t[0]; blo[nt][1] = t[1];
            blo[nt + 1][0] = t[2]; blo[nt + 1][1] = t[3];
        }
        #pragma unroll
        for (int mt = 0; mt < 2; mt++)
            #pragma unroll
            for (int nt = 0; nt < NT; nt++) {
                mma_bf16(acc[mt][nt], ahi[mt], bhi[nt]);
                mma_bf16(acc[mt][nt], ahi[mt], blo[nt]);
                mma_bf16(acc[mt][nt], alo[mt], bhi[nt]);
            }
    }

    #pragma unroll
    for (int mt = 0; mt < 2; mt++) {
        int row0 = m0 + wm * 32 + mt * 16 + (lane >> 2);
        int row1 = row0 + 8;
        float dv0 = 1.f, dv1 = 1.f;
        if (SCALE) {
            dv0 = (row0 < n) ? g_dinv[row0] : 0.f;
            dv1 = (row1 < n) ? g_dinv[row1] : 0.f;
        }
        #pragma unroll
        for (int nt = 0; nt < NT; nt++) {
            int col = wnb + nt * 8 + (lane & 3) * 2;
            if (row0 < n) {
                float2 v0 = make_float2(acc[mt][nt][0] * dv0, acc[mt][nt][1] * dv0);
                *(float2*)(out + (size_t)row0 * TN + col) = v0;
            }
            if (row1 < n) {
                float2 v1 = make_float2(acc[mt][nt][2] * dv1, acc[mt][nt][3] * dv1);
                *(float2*)(out + (size_t)row1 * TN + col) = v1;
            }
        }
    }
}

// ---------------- pull aggregation (node range [n0, n1)) ----------------
template<int D, bool SRCSCALE>
__global__ void agg_k(const float* __restrict__ tmp, const float* __restrict__ bias,
                      float* __restrict__ out, int n0, int n1) {
    int w = n0 + ((blockIdx.x * blockDim.x + threadIdx.x) >> 5);
    if (w >= n1) return;
    int l = threadIdx.x & 31;
    int s0 = g_rowptr[w], s1 = g_rowptr[w + 1];
    float dv = g_dinv[w];
    if (D == 128) {
        const float4* t = (const float4*)tmp;
        float4 sv = t[(size_t)w * 32 + l];
        float4 acc;
        if (SRCSCALE) {
            acc.x = sv.x * dv; acc.y = sv.y * dv; acc.z = sv.z * dv; acc.w = sv.w * dv;
        } else acc = sv;
        for (int j = s0; j < s1; j++) {
            int s = g_esrc[j];
            float4 v = t[(size_t)s * 32 + l];
            if (SRCSCALE) {
                float ds = g_dinv[s];
                acc.x = fmaf(v.x, ds, acc.x); acc.y = fmaf(v.y, ds, acc.y);
                acc.z = fmaf(v.z, ds, acc.z); acc.w = fmaf(v.w, ds, acc.w);
            } else {
                acc.x += v.x; acc.y += v.y; acc.z += v.z; acc.w += v.w;
            }
        }
        float4 bb = ((const float4*)bias)[l];
        float4 o;
        o.x = fmaf(acc.x, dv, bb.x); o.y = fmaf(acc.y, dv, bb.y);
        o.z = fmaf(acc.z, dv, bb.z); o.w = fmaf(acc.w, dv, bb.w);
        ((float4*)out)[(size_t)w * 32 + l] = o;
    } else {
        const float2* t = (const float2*)tmp;
        float2 acc = t[(size_t)w * 32 + l];
        for (int j = s0; j < s1; j++) {
            float2 v = t[(size_t)g_esrc[j] * 32 + l];
            acc.x += v.x; acc.y += v.y;
        }
        float2 bb = ((const float2*)bias)[l];
        float2 o;
        o.x = fmaf(acc.x, dv, bb.x); o.y = fmaf(acc.y, dv, bb.y);
        ((float2*)out)[(size_t)w * 32 + l] = o;
    }
}

// ---------------- decode ----------------
__global__ void decode_k(const float* __restrict__ z, const void* eli,
                         float* __restrict__ out, int EL) {
    int w = (blockIdx.x * blockDim.x + threadIdx.x) >> 5;
    if (w >= EL) return;
    int l = threadIdx.x & 31;
    int is64 = g_is64;
    int a = eidx(eli, (size_t)w, is64);
    int b = eidx(eli, (size_t)EL + w, is64);
    const float2* z2 = (const float2*)z;
    float2 pa = z2[(size_t)a * 32 + l];
    float2 pb = z2[(size_t)b * 32 + l];
    float p = pa.x * pb.x + pa.y * pb.y;
    #pragma unroll
    for (int off = 16; off > 0; off >>= 1)
        p += __shfl_xor_sync(0xffffffffu, p, off);
    if (l == 0) out[w] = p;
}

// ---------------- launch ----------------
extern "C" void kernel_launch(void* const* d_in, const int* in_sizes, int n_in,
                              void* d_out, int out_size) {
    const float* x  = (const float*)d_in[0];
    const void*  ei = d_in[1];
    const void*  eli= d_in[2];
    const float* W1 = (const float*)d_in[3];
    const float* b1 = (const float*)d_in[4];
    const float* W2 = (const float*)d_in[5];
    const float* b2 = (const float*)d_in[6];
    const float* W3 = (const float*)d_in[7];
    const float* b3 = (const float*)d_in[8];
    float* out = (float*)d_out;

    int N  = in_sizes[0] / 128;
    int E  = in_sizes[1] / 2;
    int EL = in_sizes[2] / 2;

    float *A, *B;
    cudaGetSymbolAddress((void**)&A, g_bufA);
    cudaGetSymbolAddress((void**)&B, g_bufB);
    __nv_bfloat16* wbase;
    cudaGetSymbolAddress((void**)&wbase, g_w);
    __nv_bfloat16* w1h = wbase;             __nv_bfloat16* w1l = wbase + 1 * 16384;
    __nv_bfloat16* w2h = wbase + 2 * 16384; __nv_bfloat16* w2l = wbase + 3 * 16384;
    __nv_bfloat16* w3h = wbase + 4 * 16384; __nv_bfloat16* w3l = wbase + 5 * 16384;

    static cudaStream_t s2 = nullptr;
    static cudaEvent_t evF, evJ, evG1, evG2a, evG2b, evG3a, evG3b, evA3b;
    if (!s2) {
        cudaStreamCreateWithFlags(&s2, cudaStreamNonBlocking);
        cudaEventCreateWithFlags(&evF,  cudaEventDisableTiming);
        cudaEventCreateWithFlags(&evJ,  cudaEventDisableTiming);
        cudaEventCreateWithFlags(&evG1, cudaEventDisableTiming);
        cudaEventCreateWithFlags(&evG2a, cudaEventDisableTiming);
        cudaEventCreateWithFlags(&evG2b, cudaEventDisableTiming);
        cudaEventCreateWithFlags(&evG3a, cudaEventDisableTiming);
        cudaEventCreateWithFlags(&evG3b, cudaEventDisableTiming);
        cudaEventCreateWithFlags(&evA3b, cudaEventDisableTiming);
    }

    int smem128 = 65536 + 2 * 128 * 256;
    int smem64  = 65536 + 2 * 64 * 256;
    cudaFuncSetAttribute(gemm_mma_k<128, false, false>, cudaFuncAttributeMaxDynamicSharedMemorySize, smem128);
    cudaFuncSetAttribute(gemm_mma_k<128, true,  true>,  cudaFuncAttributeMaxDynamicSharedMemorySize, smem128);
    cudaFuncSetAttribute(gemm_mma_k<64,  true,  true>,  cudaFuncAttributeMaxDynamicSharedMemorySize, smem64);

    int nb = (N + 511) / 512;
    int h  = (N / 2 + 127) & ~127;           // half boundary, 128-aligned
    int gg0 = (h + 127) / 128;
    int gg1 = (N - h + 127) / 128;
    int ab0 = (h * 32 + 255) / 256;
    int ab1 = ((N - h) * 32 + 255) / 256;

    // fork: preprocessing on s2
    cudaEventRecord(evF, 0);
    cudaStreamWaitEvent(s2, evF, 0);
    init_k<<<(N + 255) / 256, 256, 0, s2>>>(ei, N);
    count_k<<<(E + 255) / 256, 256, 0, s2>>>(ei, E);
    scan1_k<<<nb, 512, 0, s2>>>(N);
    scan2_k<<<1, 512, 0, s2>>>(nb);
    scan3_k<<<nb, 512, 0, s2>>>(N, E);
    fill_k<<<(E + 255) / 256, 256, 0, s2>>>(ei, E);
    cudaEventRecord(evJ, s2);

    // s0: weight splits + full layer-1 GEMM (independent of preprocessing)
    wsplit_k<128><<<(128 * 128 + 255) / 256, 256>>>(W1, w1h, w1l);
    wsplit_k<128><<<(128 * 128 + 255) / 256, 256>>>(W2, w2h, w2l);
    wsplit_k<64><<<(128 * 64 + 255) / 256, 256>>>(W3, w3h, w3l);
    gemm_mma_k<128, false, false><<<(N + 127) / 128, 256, smem128>>>(x, A, 0, N, w1h, w1l);
    cudaEventRecord(evG1, 0);

    // pipeline: half0 on s0, half1 on s2
    cudaStreamWaitEvent(0, evJ, 0);
    agg_k<128, true><<<ab0, 256>>>(A, b1, B, 0, h);
    gemm_mma_k<128, true, true><<<gg0, 256, smem128>>>(B, A, 0, h, w2h, w2l);
    cudaEventRecord(evG2a, 0);

    cudaStreamWaitEvent(s2, evG1, 0);
    agg_k<128, true><<<ab1, 256, 0, s2>>>(A, b1, B, h, N);
    gemm_mma_k<128, true, true><<<gg1, 256, smem128, s2>>>(B, A, h, N, w2h, w2l);
    cudaEventRecord(evG2b, s2);

    cudaStreamWaitEvent(0, evG2b, 0);
    agg_k<128, false><<<ab0, 256>>>(A, b2, B, 0, h);
    gemm_mma_k<64, true, true><<<gg0, 256, smem64>>>(B, A, 0, h, w3h, w3l);
    cudaEventRecord(evG3a, 0);

    cudaStreamWaitEvent(s2, evG2a, 0);
    agg_k<128, false><<<ab1, 256, 0, s2>>>(A, b2, B, h, N);
    gemm_mma_k<64, true, true><<<gg1, 256, smem64, s2>>>(B, A, h, N, w3h, w3l);
    cudaEventRecord(evG3b, s2);

    cudaStreamWaitEvent(0, evG3b, 0);
    agg_k<64, false><<<ab0, 256>>>(A, b3, B, 0, h);

    cudaStreamWaitEvent(s2, evG3a, 0);
    agg_k<64, false><<<ab1, 256, 0, s2>>>(A, b3, B, h, N);
    cudaEventRecord(evA3b, s2);

    cudaStreamWaitEvent(0, evA3b, 0);
    decode_k<<<(EL * 32 + 255) / 256, 256>>>(B, eli, out, EL);
}